// round 15
// baseline (speedup 1.0000x reference)
#include <cuda_runtime.h>
#include <cuda_bf16.h>
#include <cstdint>
#include <math.h>

#define C_    256
#define HH    30
#define WW    40
#define BB    4
#define TT    4
#define HW_   1200
#define PW2   42            // padded width (1 + 40 + 1)
#define PH2   34            // padded height (1 + 30 + 3)
#define NP    1428          // PH2*PW2 padded pixels per image
#define KW    512           // GEMM K (2 inputs * 256 ci)
#define MR    320           // GEMM M rows: 4 batches * 80 tiles (8x10 of 4x4)
#define UV    36            // 6x6 Winograd components
#define TLS   320           // total tiles
#define USLAB ((size_t)UV*MR*256)   // one A-half (256 k) transform buffer

// ---------------- scratch (device globals) ----------------------------------
__device__ __align__(256) float g_x32 [(size_t)TT*BB*NP*C_];
__device__ __align__(256) float g_h32 [(size_t)BB*NP*C_];
__device__ __align__(256) float g_cS  [(size_t)BB*NP*C_];
__device__ float g_a[BB*HW_];
__device__ __align__(256) float g_ep[(size_t)TLS*36];    // per-tile e partials
__device__ __align__(256) __nv_bfloat16 g_UHh[USLAB],    g_UHl[USLAB];     // h transform
__device__ __align__(256) __nv_bfloat16 g_UXh[TT*USLAB], g_UXl[TT*USLAB];  // x transforms
__device__ __align__(256) __nv_bfloat16 g_UTh[USLAB],    g_UTl[USLAB];     // x_tilde
__device__ __align__(256) __nv_bfloat16 g_WGh[(size_t)UV*1024*KW], g_WGl[(size_t)UV*1024*KW];
__device__ __align__(256) __nv_bfloat16 g_WAh[(size_t)UV*256*KW],  g_WAl[(size_t)UV*256*KW];
__device__ __align__(256) float g_M [(size_t)UV*MR*1024];
__device__ __align__(256) float g_Ma[(size_t)UV*MR*256];

// ---------------- PTX helpers ------------------------------------------------
#define LDSM4(arr, addr) asm volatile( \
    "ldmatrix.sync.aligned.m8n8.x4.shared.b16 {%0,%1,%2,%3}, [%4];" \
    : "=r"((arr)[0]), "=r"((arr)[1]), "=r"((arr)[2]), "=r"((arr)[3]) : "r"(addr))
#define MMA_BF16(d, a, bfr) asm volatile( \
    "mma.sync.aligned.m16n8k16.row.col.f32.bf16.bf16.f32 " \
    "{%0,%1,%2,%3}, {%4,%5,%6,%7}, {%8,%9}, {%0,%1,%2,%3};" \
    : "+f"((d)[0]), "+f"((d)[1]), "+f"((d)[2]), "+f"((d)[3]) \
    : "r"((a)[0]), "r"((a)[1]), "r"((a)[2]), "r"((a)[3]), "r"((bfr)[0]), "r"((bfr)[1]))
#define CP16(d_, s_)  asm volatile("cp.async.cg.shared.global [%0], [%1], 16;" :: "r"(d_), "l"(s_))
#define CPCOMMIT()    asm volatile("cp.async.commit_group;" ::: "memory")
#define CPWAIT1()     asm volatile("cp.async.wait_group 1;" ::: "memory")
#define CPWAIT0()     asm volatile("cp.async.wait_group 0;" ::: "memory")

__device__ __forceinline__ uint32_t s2u(const void* p){ return (uint32_t)__cvta_generic_to_shared(p); }
__device__ __forceinline__ void splitf(float v, __nv_bfloat16& h, __nv_bfloat16& l){
    h = __float2bfloat16_rn(v); l = __float2bfloat16_rn(v - __bfloat162float(h));
}

// ---------------- x NCHW -> fp32 padded channel-last ------------------------
__global__ void xprep_k(const float* __restrict__ x){
    __shared__ float tile[32][33];
    const int tx = threadIdx.x, ty = threadIdx.y;
    const int p0 = blockIdx.x*32, ci0 = blockIdx.y*32;
    const int t = blockIdx.z >> 2, b = blockIdx.z & 3;
    const float* src = x + (((size_t)b*TT + t)*C_ + ci0) * HW_;
    for (int i = ty; i < 32; i += 8){
        int p = p0 + tx;
        tile[i][tx] = (p < HW_) ? src[(size_t)i*HW_ + p] : 0.f;
    }
    __syncthreads();
    float* dst = g_x32 + ((size_t)t*BB + b)*NP*C_;
    for (int i = ty; i < 32; i += 8){
        int p = p0 + i;
        if (p >= HW_) continue;
        int q = (p/WW + 1)*PW2 + (p%WW) + 1;
        dst[(size_t)q*C_ + ci0 + tx] = tile[tx][i];
    }
}

// ---------------- F(4,3) weight transform ------------------------------------
__global__ void wtr_k(const float* __restrict__ W, int cout, int jslot,
                      __nv_bfloat16* __restrict__ Dh, __nv_bfloat16* __restrict__ Dl){
    const int co = blockIdx.x, ci = threadIdx.x;
    const float S6 = 1.f/6.f, S24 = 1.f/24.f;
    float g[3][3];
#pragma unroll
    for (int k = 0; k < 9; k++)
        g[k/3][k%3] = W[((size_t)k*C_ + ci)*cout + co];
    float u[6][3];
#pragma unroll
    for (int c = 0; c < 3; c++){
        float a = g[0][c], b = g[1][c], cc = g[2][c];
        u[0][c] = 0.25f*a;
        u[1][c] = -S6*(a + b + cc);
        u[2][c] = -S6*(a - b + cc);
        u[3][c] = S24*(a + 2.f*b + 4.f*cc);
        u[4][c] = S24*(a - 2.f*b + 4.f*cc);
        u[5][c] = cc;
    }
#pragma unroll
    for (int i = 0; i < 6; i++){
        float a = u[i][0], b = u[i][1], cc = u[i][2];
        float w[6] = { 0.25f*a, -S6*(a + b + cc), -S6*(a - b + cc),
                       S24*(a + 2.f*b + 4.f*cc), S24*(a - 2.f*b + 4.f*cc), cc };
#pragma unroll
        for (int j = 0; j < 6; j++){
            __nv_bfloat16 h, l; splitf(w[j], h, l);
            size_t o = ((size_t)(i*6+j)*cout + co)*KW + jslot*256 + ci;
            Dh[o] = h; Dl[o] = l;
        }
    }
}

// ---------------- F(4,3) input transform core (256-k-wide A slabs) ----------
__device__ __forceinline__ void wino_in(const float d[6][6],
                                        __nv_bfloat16* __restrict__ Dh,
                                        __nv_bfloat16* __restrict__ Dl,
                                        int tt, int ci){
    float t[6][6];
#pragma unroll
    for (int c = 0; c < 6; c++){
        float d0=d[0][c], d1=d[1][c], d2=d[2][c], d3=d[3][c], d4=d[4][c], d5=d[5][c];
        t[0][c] = 4.f*d0 - 5.f*d2 + d4;
        t[1][c] = -4.f*d1 - 4.f*d2 + d3 + d4;
        t[2][c] =  4.f*d1 - 4.f*d2 - d3 + d4;
        t[3][c] = -2.f*d1 - d2 + 2.f*d3 + d4;
        t[4][c] =  2.f*d1 - d2 - 2.f*d3 + d4;
        t[5][c] =  4.f*d1 - 5.f*d3 + d5;
    }
#pragma unroll
    for (int r = 0; r < 6; r++){
        float v0=t[r][0], v1=t[r][1], v2=t[r][2], v3=t[r][3], v4=t[r][4], v5=t[r][5];
        float w[6] = { 4.f*v0 - 5.f*v2 + v4,
                       -4.f*v1 - 4.f*v2 + v3 + v4,
                        4.f*v1 - 4.f*v2 - v3 + v4,
                       -2.f*v1 - v2 + 2.f*v3 + v4,
                        2.f*v1 - v2 - 2.f*v3 + v4,
                        4.f*v1 - 5.f*v3 + v5 };
#pragma unroll
        for (int j = 0; j < 6; j++){
            __nv_bfloat16 h, l; splitf(w[j], h, l);
            size_t o = ((size_t)(r*6+j)*MR + tt)*256 + ci;
            Dh[o] = h; Dl[o] = l;
        }
    }
}

// ---------------- h input transform (per step) -------------------------------
__global__ void itrH_k(){
    const int tt = blockIdx.x, ci = threadIdx.x;
    const int b = tt/80, rr = tt%80, ty = rr/10, tx = rr%10;
    const float* src = g_h32 + ((size_t)b*NP + 4*ty*PW2 + 4*tx)*C_ + ci;
    float d[6][6];
#pragma unroll
    for (int r = 0; r < 6; r++)
#pragma unroll
        for (int c = 0; c < 6; c++)
            d[r][c] = src[(size_t)(r*PW2 + c)*C_];
    wino_in(d, g_UHh, g_UHl, tt, ci);
}

// ---------------- x input transforms (all t, once) ---------------------------
__global__ void itrXall_k(){
    const int tt = blockIdx.x, t = blockIdx.y, ci = threadIdx.x;
    const int b = tt/80, rr = tt%80, ty = rr/10, tx = rr%10;
    const float* src = g_x32 + ((size_t)(t*BB + b)*NP + 4*ty*PW2 + 4*tx)*C_ + ci;
    float d[6][6];
#pragma unroll
    for (int r = 0; r < 6; r++)
#pragma unroll
        for (int c = 0; c < 6; c++)
            d[r][c] = src[(size_t)(r*PW2 + c)*C_];
    wino_in(d, g_UXh + t*USLAB, g_UXl + t*USLAB, tt, ci);
}

// ---------------- x_tilde = x*a input transform (per step) ------------------
__global__ void itrX_k(const float* __restrict__ xsrc){
    __shared__ float a_s[36];
    const int tt = blockIdx.x, ci = threadIdx.x;
    const int b = tt/80, rr = tt%80, ty = rr/10, tx = rr%10;
    if (ci < 36){
        int r = ci/6, c = ci%6;
        int py = 4*ty + r - 1, px = 4*tx + c - 1;
        a_s[ci] = ((unsigned)py < (unsigned)HH && (unsigned)px < (unsigned)WW)
                  ? g_a[b*HW_ + py*WW + px] : 0.f;
    }
    __syncthreads();
    const float* src = xsrc + ((size_t)b*NP + 4*ty*PW2 + 4*tx)*C_ + ci;
    float d[6][6];
#pragma unroll
    for (int r = 0; r < 6; r++)
#pragma unroll
        for (int c = 0; c < 6; c++)
            d[r][c] = src[(size_t)(r*PW2 + c)*C_] * a_s[r*6 + c];
    wino_in(d, g_UTh, g_UTl, tt, ci);
}

// ---------------- GEMM: M[uv][row][co] = [A1|A2] . Wt^T  (bf16x3 HMMA) ------
template<int COUT>
__global__ __launch_bounds__(256, 2)
void gemm_k(const __nv_bfloat16* __restrict__ A1h, const __nv_bfloat16* __restrict__ A1l,
            const __nv_bfloat16* __restrict__ A2h, const __nv_bfloat16* __restrict__ A2l,
            const __nv_bfloat16* __restrict__ Wh_g, const __nv_bfloat16* __restrict__ Wl_g,
            float* __restrict__ Mout)
{
    extern __shared__ char smem[];
    const uint32_t sb0 = s2u(smem);
    const int tid = threadIdx.x, lane = tid & 31, wid = tid >> 5;
    const int m0 = blockIdx.x*64, n0 = blockIdx.y*128, uv = blockIdx.z;
    const size_t Ao = ((size_t)uv*MR + m0)*256;
    const size_t Bb = ((size_t)uv*COUT + n0)*KW;

    auto stage = [&](int kc, int s){
        const uint32_t sb = sb0 + s*55296;
        const __nv_bfloat16* a_h = (kc < 4) ? A1h : A2h;
        const __nv_bfloat16* a_l = (kc < 4) ? A1l : A2l;
        const int kk = (kc & 3)*64;
#pragma unroll
        for (int u = 0; u < 12; u++){
            int idx = tid + (u << 8);
            const __nv_bfloat16* src; uint32_t dst;
            if (idx < 1024){
                int hl = idx >> 9, w = idx & 511, r = w >> 3, c = w & 7;
                src = (hl ? a_l : a_h) + Ao + (size_t)r*256 + kk + c*8;
                dst = sb + hl*9216 + (r*72 + c*8)*2;
            } else {
                int w = idx - 1024; int hl = w >> 10; w &= 1023;
                int r = w >> 3, c = w & 7;
                src = (hl ? Wl_g : Wh_g) + Bb + (size_t)r*KW + kc*64 + c*8;
                dst = sb + 18432 + hl*18432 + (r*72 + c*8)*2;
            }
            CP16(dst, src);
        }
        CPCOMMIT();
    };

    float acc[2][4][4];
#pragma unroll
    for (int mt = 0; mt < 2; mt++)
#pragma unroll
        for (int nf = 0; nf < 4; nf++)
#pragma unroll
            for (int e = 0; e < 4; e++) acc[mt][nf][e] = 0.f;

    const int lr = lane & 7, ls = lane >> 3;
    const int arow = ((ls & 1) << 3) + lr, acol = (ls >> 1) << 3;
    const int brow = ((ls >> 1) << 3) + lr, bcol = (ls & 1) << 3;
    const int wm = (wid & 1)*32, wn = (wid >> 1)*32;

    stage(0, 0);
#pragma unroll 1
    for (int kc = 0; kc < 8; kc++){
        if (kc < 7){ stage(kc+1, (kc+1) & 1); CPWAIT1(); } else CPWAIT0();
        __syncthreads();
        const uint32_t sA = sb0 + (kc & 1)*55296;
        const uint32_t sB = sA + 18432;
#pragma unroll
        for (int k16 = 0; k16 < 4; k16++){
            const int kcc = k16*16;
            uint32_t bh[4][2], bl[4][2];
#pragma unroll
            for (int g = 0; g < 2; g++){
                uint32_t tb[4];
                uint32_t ra = sB + ((wn + g*16 + brow)*72 + kcc + bcol)*2;
                LDSM4(tb, ra);
                bh[2*g][0]=tb[0]; bh[2*g][1]=tb[1]; bh[2*g+1][0]=tb[2]; bh[2*g+1][1]=tb[3];
                LDSM4(tb, ra + 18432);
                bl[2*g][0]=tb[0]; bl[2*g][1]=tb[1]; bl[2*g+1][0]=tb[2]; bl[2*g+1][1]=tb[3];
            }
#pragma unroll
            for (int mt = 0; mt < 2; mt++){
                uint32_t ah[4], al[4];
                uint32_t ra = sA + ((wm + mt*16 + arow)*72 + kcc + acol)*2;
                LDSM4(ah, ra);
                LDSM4(al, ra + 9216);
#pragma unroll
                for (int nf = 0; nf < 4; nf++){
                    MMA_BF16(acc[mt][nf], ah, bh[nf]);
                    MMA_BF16(acc[mt][nf], al, bh[nf]);
                    MMA_BF16(acc[mt][nf], ah, bl[nf]);
                }
            }
        }
        __syncthreads();
    }

    const int g2 = lane >> 2, cg = (lane & 3)*2;
#pragma unroll
    for (int nf = 0; nf < 4; nf++){
        int col = n0 + wn + nf*8 + cg;
#pragma unroll
        for (int mt = 0; mt < 2; mt++){
            int row = m0 + wm + mt*16 + g2;
            *(float2*)&Mout[((size_t)uv*MR + row)*COUT + col]     = make_float2(acc[mt][nf][0], acc[mt][nf][1]);
            *(float2*)&Mout[((size_t)uv*MR + row + 8)*COUT + col] = make_float2(acc[mt][nf][2], acc[mt][nf][3]);
        }
    }
}

// ---------------- F(4,3) output transform core -------------------------------
__device__ __forceinline__ void wino_out(const float m[6][6], float y[4][4]){
    float z[4][6];
#pragma unroll
    for (int c = 0; c < 6; c++){
        float m1 = m[1][c], m2 = m[2][c], m3 = m[3][c], m4 = m[4][c];
        z[0][c] = m[0][c] + m1 + m2 + m3 + m4;
        z[1][c] = m1 - m2 + 2.f*(m3 - m4);
        z[2][c] = m1 + m2 + 4.f*(m3 + m4);
        z[3][c] = m1 - m2 + 8.f*(m3 - m4) + m[5][c];
    }
#pragma unroll
    for (int r = 0; r < 4; r++){
        float v1 = z[r][1], v2 = z[r][2], v3 = z[r][3], v4 = z[r][4];
        y[r][0] = z[r][0] + v1 + v2 + v3 + v4;
        y[r][1] = v1 - v2 + 2.f*(v3 - v4);
        y[r][2] = v1 + v2 + 4.f*(v3 + v4);
        y[r][3] = v1 - v2 + 8.f*(v3 - v4) + z[r][5];
    }
}

// ---------------- attention output transform + fused e-partials -------------
// Computes att = tanh(conv+bias) on the fly and accumulates its contribution
// to the 6x6 e-neighborhood of this tile:  e(p') = sum att(p)*Va[p'-p+1].
__global__ void otrAe_k(const float* __restrict__ Msrc, const float* __restrict__ b1,
                        const float* __restrict__ b2, const float* __restrict__ Va){
    __shared__ float sEP[8][36];
    const int tt = blockIdx.x, co = threadIdx.x;
    const int rr = tt%80, ty = rr/10, tx = rr%10;
    float m[6][6];
#pragma unroll
    for (int uv = 0; uv < UV; uv++)
        m[uv/6][uv%6] = Msrc[((size_t)uv*MR + tt)*256 + co];
    float y[4][4];
    wino_out(m, y);
    const float bz = __ldg(b1 + co) + __ldg(b2 + co);

    float va[9];
#pragma unroll
    for (int k = 0; k < 9; k++) va[k] = __ldg(Va + k*C_ + co);

    float ep[6][6];
#pragma unroll
    for (int i = 0; i < 36; i++) ep[i/6][i%6] = 0.f;
#pragma unroll
    for (int r = 0; r < 4; r++){
        int oy = 4*ty + r;
        if (oy >= HH) continue;
#pragma unroll
        for (int c = 0; c < 4; c++){
            float av = tanhf(y[r][c] + bz);
            // att(y,x) contributes to e(y+d, x+dd) with weight Va[(1-d)*3+(1-dd)]
#pragma unroll
            for (int d = -1; d <= 1; d++)
#pragma unroll
                for (int dd = -1; dd <= 1; dd++)
                    ep[r+1+d][c+1+dd] += av * va[(1-d)*3 + (1-dd)];
        }
    }
    // reduce over 256 threads (deterministic tree)
    const int lane = co & 31, wrp = co >> 5;
#pragma unroll
    for (int l = 0; l < 36; l++){
        float v = ep[l/6][l%6];
#pragma unroll
        for (int o = 16; o > 0; o >>= 1) v += __shfl_xor_sync(0xFFFFFFFF, v, o);
        if (lane == 0) sEP[wrp][l] = v;
    }
    __syncthreads();
    if (co < 36){
        float s = 0.f;
#pragma unroll
        for (int w = 0; w < 8; w++) s += sEP[w][co];
        g_ep[(size_t)tt*36 + co] = s;
    }
}

// ---------------- softmax over H*W per batch (gathers e from tile partials) --
__global__ void softmax_k(){
    __shared__ float se[HW_];
    __shared__ float red[256];
    const int b = blockIdx.x;
    for (int i = threadIdx.x; i < HW_; i += 256){
        int y = i / WW, x = i % WW;
        float e = 0.f;
        int tyh = (y+1) >> 2, txh = (x+1) >> 2;
#pragma unroll
        for (int a_ = 0; a_ < 2; a_++){
            int ty = tyh - a_;
            if (ty < 0 || ty > 7) continue;
            int ly = y - 4*ty + 1;
            if (ly < 0 || ly > 5) continue;
#pragma unroll
            for (int bb = 0; bb < 2; bb++){
                int tx = txh - bb;
                if (tx < 0 || tx > 9) continue;
                int lx = x - 4*tx + 1;
                if (lx < 0 || lx > 5) continue;
                e += g_ep[(size_t)(b*80 + ty*10 + tx)*36 + ly*6 + lx];
            }
        }
        se[i] = e;
    }
    __syncthreads();
    float mx = -1e30f;
    for (int i = threadIdx.x; i < HW_; i += 256) mx = fmaxf(mx, se[i]);
    red[threadIdx.x] = mx; __syncthreads();
    for (int s = 128; s > 0; s >>= 1){
        if (threadIdx.x < s) red[threadIdx.x] = fmaxf(red[threadIdx.x], red[threadIdx.x+s]);
        __syncthreads();
    }
    mx = red[0]; __syncthreads();
    float sum = 0.f;
    for (int i = threadIdx.x; i < HW_; i += 256) sum += expf(se[i] - mx);
    red[threadIdx.x] = sum; __syncthreads();
    for (int s = 128; s > 0; s >>= 1){
        if (threadIdx.x < s) red[threadIdx.x] += red[threadIdx.x+s];
        __syncthreads();
    }
    float inv = 1.f / red[0];
    for (int i = threadIdx.x; i < HW_; i += 256)
        g_a[b*HW_ + i] = expf(se[i] - mx) * inv;
}

// ---------------- gate output transform + LSTM update (fused) ---------------
__global__ void otrl_k(const float* __restrict__ Msrc, const float* __restrict__ b1,
                       const float* __restrict__ b2, float* __restrict__ outp){
    const int tt = blockIdx.x, co = threadIdx.x;
    const int b = tt/80, rr = tt%80, ty = rr/10, tx = rr%10;
    float yg[4][4][4];
#pragma unroll
    for (int g = 0; g < 4; g++){
        float m[6][6];
#pragma unroll
        for (int uv = 0; uv < UV; uv++)
            m[uv/6][uv%6] = Msrc[((size_t)uv*MR + tt)*1024 + g*256 + co];
        wino_out(m, yg[g]);
    }
    float bz[4];
#pragma unroll
    for (int g = 0; g < 4; g++)
        bz[g] = __ldg(b1 + g*256 + co) + __ldg(b2 + g*256 + co);
#pragma unroll
    for (int r = 0; r < 4; r++){
        int oy = 4*ty + r;
        if (oy >= HH) continue;
#pragma unroll
        for (int c = 0; c < 4; c++){
            int px = 4*tx + c;
            int pix = (oy + 1)*PW2 + px + 1;
            size_t cx = ((size_t)(b*NP + pix))*C_ + co;
            float iv = 1.f/(1.f + expf(-(yg[0][r][c] + bz[0])));
            float fv = 1.f/(1.f + expf(-(yg[1][r][c] + bz[1])));
            float cc = tanhf(yg[2][r][c] + bz[2]);
            float ov = 1.f/(1.f + expf(-(yg[3][r][c] + bz[3])));
            float cn = fv*g_cS[cx] + iv*cc;
            float hn = ov*tanhf(cn);
            g_cS[cx] = cn;
            g_h32[cx] = hn;
            if (outp) outp[((size_t)(b*C_ + co))*HW_ + oy*WW + px] = hn;
        }
    }
}

// ---------------- h0 = c0 = sum_t x ------------------------------------------
__global__ void init_hc_k(){
    int i = blockIdx.x*blockDim.x + threadIdx.x;
    if (i >= BB*HW_*C_) return;
    int ci = i & 255, rest = i >> 8;
    int p = rest % HW_, b = rest / HW_;
    int q = (p/WW + 1)*PW2 + (p%WW) + 1;
    float s = 0.f;
#pragma unroll
    for (int t = 0; t < TT; t++)
        s += g_x32[(((size_t)t*BB + b)*NP + q)*C_ + ci];
    size_t o = ((size_t)b*NP + q)*C_ + ci;
    g_cS[o] = s;
    g_h32[o] = s;
}

// -----------------------------------------------------------------------------
extern "C" void kernel_launch(void* const* d_in, const int* in_sizes, int n_in,
                              void* d_out, int out_size)
{
    const float* x   = (const float*)d_in[0];
    const float* Wa  = (const float*)d_in[1];
    const float* ba  = (const float*)d_in[2];
    const float* Ua  = (const float*)d_in[3];
    const float* bua = (const float*)d_in[4];
    const float* Va  = (const float*)d_in[5];
    const float* Wx  = (const float*)d_in[6];
    const float* bx  = (const float*)d_in[7];
    const float* Uh  = (const float*)d_in[8];
    const float* bh  = (const float*)d_in[9];
    float* out = (float*)d_out;

    void *pX, *pH, *pWAh, *pWAl, *pWGh, *pWGl, *pM, *pMa;
    void *pUHh, *pUHl, *pUXh, *pUXl, *pUTh, *pUTl;
    cudaGetSymbolAddress(&pX,  g_x32);
    cudaGetSymbolAddress(&pH,  g_h32);
    cudaGetSymbolAddress(&pWAh, g_WAh); cudaGetSymbolAddress(&pWAl, g_WAl);
    cudaGetSymbolAddress(&pWGh, g_WGh); cudaGetSymbolAddress(&pWGl, g_WGl);
    cudaGetSymbolAddress(&pM,  g_M);    cudaGetSymbolAddress(&pMa, g_Ma);
    cudaGetSymbolAddress(&pUHh, g_UHh); cudaGetSymbolAddress(&pUHl, g_UHl);
    cudaGetSymbolAddress(&pUXh, g_UXh); cudaGetSymbolAddress(&pUXl, g_UXl);
    cudaGetSymbolAddress(&pUTh, g_UTh); cudaGetSymbolAddress(&pUTl, g_UTl);

    const int SMEM = 2*55296;   // 110,592 B double-buffered stage
    cudaFuncSetAttribute(gemm_k<256>,  cudaFuncAttributeMaxDynamicSharedMemorySize, SMEM);
    cudaFuncSetAttribute(gemm_k<1024>, cudaFuncAttributeMaxDynamicSharedMemorySize, SMEM);

    // zero padded borders (interiors rewritten each call)
    cudaMemsetAsync(pX, 0, sizeof(float)*(size_t)TT*BB*NP*C_);
    cudaMemsetAsync(pH, 0, sizeof(float)*(size_t)BB*NP*C_);

    xprep_k<<<dim3(38, 8, 16), dim3(32, 8)>>>(x);
    wtr_k<<<256,  256>>>(Wa, 256,  0, (__nv_bfloat16*)pWAh, (__nv_bfloat16*)pWAl);
    wtr_k<<<256,  256>>>(Ua, 256,  1, (__nv_bfloat16*)pWAh, (__nv_bfloat16*)pWAl);
    wtr_k<<<1024, 256>>>(Uh, 1024, 0, (__nv_bfloat16*)pWGh, (__nv_bfloat16*)pWGl);
    wtr_k<<<1024, 256>>>(Wx, 1024, 1, (__nv_bfloat16*)pWGh, (__nv_bfloat16*)pWGl);

    const int NPT = BB*HW_*C_, NB = (NPT + 255)/256;
    init_hc_k<<<NB, 256>>>();
    itrXall_k<<<dim3(TLS, TT), 256>>>();   // all x_t transforms, once

    const float* x32 = (const float*)pX;
    const size_t ts = (size_t)BB*NP*C_;

    for (int t = 0; t < TT; t++){
        // attention: att = tanh(conv(h,Wa)+ba + conv(x_t,Ua)+bua); e fused into otrAe
        itrH_k<<<TLS, 256>>>();
        gemm_k<256><<<dim3(5, 2, UV), 256, SMEM>>>(
            (const __nv_bfloat16*)pUHh, (const __nv_bfloat16*)pUHl,
            (const __nv_bfloat16*)pUXh + t*USLAB, (const __nv_bfloat16*)pUXl + t*USLAB,
            (const __nv_bfloat16*)pWAh, (const __nv_bfloat16*)pWAl, (float*)pMa);
        otrAe_k<<<TLS, 256>>>((const float*)pMa, ba, bua, Va);
        softmax_k<<<BB, 256>>>();

        // gates: g = conv(x*a,Wx)+bx + conv(h,Uh)+bh ; then LSTM update
        itrX_k<<<TLS, 256>>>(x32 + t*ts);
        gemm_k<1024><<<dim3(5, 8, UV), 256, SMEM>>>(
            (const __nv_bfloat16*)pUHh, (const __nv_bfloat16*)pUHl,
            (const __nv_bfloat16*)pUTh, (const __nv_bfloat16*)pUTl,
            (const __nv_bfloat16*)pWGh, (const __nv_bfloat16*)pWGl, (float*)pM);
        otrl_k<<<TLS, 256>>>((const float*)pM, bx, bh, (t == TT-1) ? out : (float*)nullptr);
    }
}

// round 17
// speedup vs baseline: 1.0025x; 1.0025x over previous
#include <cuda_runtime.h>
#include <cuda_bf16.h>
#include <cstdint>
#include <math.h>

#define C_    256
#define HH    30
#define WW    40
#define BB    4
#define TT    4
#define HW_   1200
#define PW2   42            // padded width (1 + 40 + 1)
#define PH2   34            // padded height (1 + 30 + 3)
#define NP    1428          // PH2*PW2 padded pixels per image
#define KW    512           // GEMM K (2 inputs * 256 ci)
#define MR    320           // GEMM M rows: 4 batches * 80 tiles (8x10 of 4x4)
#define UV    36            // 6x6 Winograd components
#define TLS   320           // total tiles
#define USLAB ((size_t)UV*MR*256)   // one A-half (256 k) transform buffer

// ---------------- scratch (device globals; zero-initialized at load) --------
__device__ __align__(256) float g_x32 [(size_t)TT*BB*NP*C_];
__device__ __align__(256) float g_h32 [(size_t)BB*NP*C_];
__device__ __align__(256) float g_cS  [(size_t)BB*NP*C_];
__device__ __align__(256) float g_ep[(size_t)TLS*36];    // per-tile e partials
__device__ __align__(256) __nv_bfloat16 g_UHh[USLAB],    g_UHl[USLAB];     // h transform
__device__ __align__(256) __nv_bfloat16 g_UXh[TT*USLAB], g_UXl[TT*USLAB];  // x transforms
__device__ __align__(256) __nv_bfloat16 g_UTh[USLAB],    g_UTl[USLAB];     // x_tilde
__device__ __align__(256) __nv_bfloat16 g_WGh[(size_t)UV*1024*KW], g_WGl[(size_t)UV*1024*KW];
__device__ __align__(256) __nv_bfloat16 g_WAh[(size_t)UV*256*KW],  g_WAl[(size_t)UV*256*KW];
__device__ __align__(256) float g_M [(size_t)UV*MR*1024];
__device__ __align__(256) float g_Ma[(size_t)UV*MR*256];

// ---------------- PTX helpers ------------------------------------------------
#define LDSM4(arr, addr) asm volatile( \
    "ldmatrix.sync.aligned.m8n8.x4.shared.b16 {%0,%1,%2,%3}, [%4];" \
    : "=r"((arr)[0]), "=r"((arr)[1]), "=r"((arr)[2]), "=r"((arr)[3]) : "r"(addr))
#define MMA_BF16(d, a, bfr) asm volatile( \
    "mma.sync.aligned.m16n8k16.row.col.f32.bf16.bf16.f32 " \
    "{%0,%1,%2,%3}, {%4,%5,%6,%7}, {%8,%9}, {%0,%1,%2,%3};" \
    : "+f"((d)[0]), "+f"((d)[1]), "+f"((d)[2]), "+f"((d)[3]) \
    : "r"((a)[0]), "r"((a)[1]), "r"((a)[2]), "r"((a)[3]), "r"((bfr)[0]), "r"((bfr)[1]))
#define CP16(d_, s_)  asm volatile("cp.async.cg.shared.global [%0], [%1], 16;" :: "r"(d_), "l"(s_))
#define CPCOMMIT()    asm volatile("cp.async.commit_group;" ::: "memory")
#define CPWAIT1()     asm volatile("cp.async.wait_group 1;" ::: "memory")
#define CPWAIT0()     asm volatile("cp.async.wait_group 0;" ::: "memory")

__device__ __forceinline__ uint32_t s2u(const void* p){ return (uint32_t)__cvta_generic_to_shared(p); }
__device__ __forceinline__ void splitf(float v, __nv_bfloat16& h, __nv_bfloat16& l){
    h = __float2bfloat16_rn(v); l = __float2bfloat16_rn(v - __bfloat162float(h));
}

// ---------------- x NCHW -> fp32 padded channel-last ------------------------
__global__ void xprep_k(const float* __restrict__ x){
    __shared__ float tile[32][33];
    const int tx = threadIdx.x, ty = threadIdx.y;
    const int p0 = blockIdx.x*32, ci0 = blockIdx.y*32;
    const int t = blockIdx.z >> 2, b = blockIdx.z & 3;
    const float* src = x + (((size_t)b*TT + t)*C_ + ci0) * HW_;
    for (int i = ty; i < 32; i += 8){
        int p = p0 + tx;
        tile[i][tx] = (p < HW_) ? src[(size_t)i*HW_ + p] : 0.f;
    }
    __syncthreads();
    float* dst = g_x32 + ((size_t)t*BB + b)*NP*C_;
    for (int i = ty; i < 32; i += 8){
        int p = p0 + i;
        if (p >= HW_) continue;
        int q = (p/WW + 1)*PW2 + (p%WW) + 1;
        dst[(size_t)q*C_ + ci0 + tx] = tile[tx][i];
    }
}

// ---------------- F(4,3) weight transform (coalesced, fully parallel) --------
// grid (cout/32, 8), block (32,8). Reads co-coalesced via smem transpose;
// writes stay ci-coalesced. Each thread computes 4 (ci,co) pairs.
__global__ void wtr_k(const float* __restrict__ W, int cout, int jslot,
                      __nv_bfloat16* __restrict__ Dh, __nv_bfloat16* __restrict__ Dl){
    __shared__ float tl[9][32][33];     // [k][ci][co]
    const int co0 = blockIdx.x*32, ci0 = blockIdx.y*32;
    const int tx = threadIdx.x, ty = threadIdx.y;
    const float S6 = 1.f/6.f, S24 = 1.f/24.f;
    for (int idx = ty; idx < 288; idx += 8){
        int k = idx >> 5, ci = idx & 31;
        tl[k][ci][tx] = W[((size_t)k*C_ + ci0 + ci)*cout + co0 + tx];
    }
    __syncthreads();
    const int ci = tx;
#pragma unroll
    for (int jj = 0; jj < 4; jj++){
        const int cs = ty + 8*jj;       // co - co0
        const int co = co0 + cs;
        float g[3][3];
#pragma unroll
        for (int k = 0; k < 9; k++) g[k/3][k%3] = tl[k][ci][cs];
        float u[6][3];
#pragma unroll
        for (int c = 0; c < 3; c++){
            float a = g[0][c], b = g[1][c], cc = g[2][c];
            u[0][c] = 0.25f*a;
            u[1][c] = -S6*(a + b + cc);
            u[2][c] = -S6*(a - b + cc);
            u[3][c] = S24*(a + 2.f*b + 4.f*cc);
            u[4][c] = S24*(a - 2.f*b + 4.f*cc);
            u[5][c] = cc;
        }
#pragma unroll
        for (int i = 0; i < 6; i++){
            float a = u[i][0], b = u[i][1], cc = u[i][2];
            float w[6] = { 0.25f*a, -S6*(a + b + cc), -S6*(a - b + cc),
                           S24*(a + 2.f*b + 4.f*cc), S24*(a - 2.f*b + 4.f*cc), cc };
#pragma unroll
            for (int j = 0; j < 6; j++){
                __nv_bfloat16 h, l; splitf(w[j], h, l);
                size_t o = ((size_t)(i*6+j)*cout + co)*KW + jslot*256 + ci0 + ci;
                Dh[o] = h; Dl[o] = l;
            }
        }
    }
}

// ---------------- F(4,3) input transform core (256-k-wide A slabs) ----------
__device__ __forceinline__ void wino_in(const float d[6][6],
                                        __nv_bfloat16* __restrict__ Dh,
                                        __nv_bfloat16* __restrict__ Dl,
                                        int tt, int ci){
    float t[6][6];
#pragma unroll
    for (int c = 0; c < 6; c++){
        float d0=d[0][c], d1=d[1][c], d2=d[2][c], d3=d[3][c], d4=d[4][c], d5=d[5][c];
        t[0][c] = 4.f*d0 - 5.f*d2 + d4;
        t[1][c] = -4.f*d1 - 4.f*d2 + d3 + d4;
        t[2][c] =  4.f*d1 - 4.f*d2 - d3 + d4;
        t[3][c] = -2.f*d1 - d2 + 2.f*d3 + d4;
        t[4][c] =  2.f*d1 - d2 - 2.f*d3 + d4;
        t[5][c] =  4.f*d1 - 5.f*d3 + d5;
    }
#pragma unroll
    for (int r = 0; r < 6; r++){
        float v0=t[r][0], v1=t[r][1], v2=t[r][2], v3=t[r][3], v4=t[r][4], v5=t[r][5];
        float w[6] = { 4.f*v0 - 5.f*v2 + v4,
                       -4.f*v1 - 4.f*v2 + v3 + v4,
                        4.f*v1 - 4.f*v2 - v3 + v4,
                       -2.f*v1 - v2 + 2.f*v3 + v4,
                        2.f*v1 - v2 - 2.f*v3 + v4,
                        4.f*v1 - 5.f*v3 + v5 };
#pragma unroll
        for (int j = 0; j < 6; j++){
            __nv_bfloat16 h, l; splitf(w[j], h, l);
            size_t o = ((size_t)(r*6+j)*MR + tt)*256 + ci;
            Dh[o] = h; Dl[o] = l;
        }
    }
}

// ---------------- h input transform (per step) -------------------------------
__global__ void itrH_k(){
    const int tt = blockIdx.x, ci = threadIdx.x;
    const int b = tt/80, rr = tt%80, ty = rr/10, tx = rr%10;
    const float* src = g_h32 + ((size_t)b*NP + 4*ty*PW2 + 4*tx)*C_ + ci;
    float d[6][6];
#pragma unroll
    for (int r = 0; r < 6; r++)
#pragma unroll
        for (int c = 0; c < 6; c++)
            d[r][c] = src[(size_t)(r*PW2 + c)*C_];
    wino_in(d, g_UHh, g_UHl, tt, ci);
}

// ---------------- x input transforms (all t, once) ---------------------------
__global__ void itrXall_k(){
    const int tt = blockIdx.x, t = blockIdx.y, ci = threadIdx.x;
    const int b = tt/80, rr = tt%80, ty = rr/10, tx = rr%10;
    const float* src = g_x32 + ((size_t)(t*BB + b)*NP + 4*ty*PW2 + 4*tx)*C_ + ci;
    float d[6][6];
#pragma unroll
    for (int r = 0; r < 6; r++)
#pragma unroll
        for (int c = 0; c < 6; c++)
            d[r][c] = src[(size_t)(r*PW2 + c)*C_];
    wino_in(d, g_UXh + t*USLAB, g_UXl + t*USLAB, tt, ci);
}

// ---------------- fused softmax + x_tilde transform (per step) --------------
// Each block redundantly recomputes its batch's softmax from g_ep partials
// (deterministic: same reduction order in every block), then transforms
// x_tilde = x * a for its tile.
__global__ void itrXs_k(const float* __restrict__ xsrc){
    __shared__ float se[HW_];
    __shared__ float red[256];
    __shared__ float a_s[36];
    const int tt = blockIdx.x, ci = threadIdx.x;
    const int b = tt/80, rr = tt%80, ty = rr/10, tx = rr%10;

    // gather e from tile partials
    for (int i = ci; i < HW_; i += 256){
        int y = i / WW, x = i % WW;
        float e = 0.f;
        int tyh = (y+1) >> 2, txh = (x+1) >> 2;
#pragma unroll
        for (int a_ = 0; a_ < 2; a_++){
            int ty2 = tyh - a_;
            if (ty2 < 0 || ty2 > 7) continue;
            int ly = y - 4*ty2 + 1;
            if (ly < 0 || ly > 5) continue;
#pragma unroll
            for (int bb = 0; bb < 2; bb++){
                int tx2 = txh - bb;
                if (tx2 < 0 || tx2 > 9) continue;
                int lx = x - 4*tx2 + 1;
                if (lx < 0 || lx > 5) continue;
                e += g_ep[(size_t)(b*80 + ty2*10 + tx2)*36 + ly*6 + lx];
            }
        }
        se[i] = e;
    }
    __syncthreads();
    float mx = -1e30f;
    for (int i = ci; i < HW_; i += 256) mx = fmaxf(mx, se[i]);
    red[ci] = mx; __syncthreads();
    for (int s = 128; s > 0; s >>= 1){
        if (ci < s) red[ci] = fmaxf(red[ci], red[ci+s]);
        __syncthreads();
    }
    mx = red[0]; __syncthreads();
    float sum = 0.f;
    for (int i = ci; i < HW_; i += 256) sum += expf(se[i] - mx);
    red[ci] = sum; __syncthreads();
    for (int s = 128; s > 0; s >>= 1){
        if (ci < s) red[ci] += red[ci+s];
        __syncthreads();
    }
    const float inv = 1.f / red[0];

    if (ci < 36){
        int r = ci/6, c = ci%6;
        int py = 4*ty + r - 1, px = 4*tx + c - 1;
        a_s[ci] = ((unsigned)py < (unsigned)HH && (unsigned)px < (unsigned)WW)
                  ? expf(se[py*WW + px] - mx) * inv : 0.f;
    }
    __syncthreads();

    const float* src = xsrc + ((size_t)b*NP + 4*ty*PW2 + 4*tx)*C_ + ci;
    float d[6][6];
#pragma unroll
    for (int r = 0; r < 6; r++)
#pragma unroll
        for (int c = 0; c < 6; c++)
            d[r][c] = src[(size_t)(r*PW2 + c)*C_] * a_s[r*6 + c];
    wino_in(d, g_UTh, g_UTl, tt, ci);
}

// ---------------- GEMM: M[uv][row][co] = [A1|A2] . Wt^T  (bf16x3 HMMA) ------
template<int COUT>
__global__ __launch_bounds__(256, 2)
void gemm_k(const __nv_bfloat16* __restrict__ A1h, const __nv_bfloat16* __restrict__ A1l,
            const __nv_bfloat16* __restrict__ A2h, const __nv_bfloat16* __restrict__ A2l,
            const __nv_bfloat16* __restrict__ Wh_g, const __nv_bfloat16* __restrict__ Wl_g,
            float* __restrict__ Mout)
{
    extern __shared__ char smem[];
    const uint32_t sb0 = s2u(smem);
    const int tid = threadIdx.x, lane = tid & 31, wid = tid >> 5;
    const int m0 = blockIdx.x*64, n0 = blockIdx.y*128, uv = blockIdx.z;
    const size_t Ao = ((size_t)uv*MR + m0)*256;
    const size_t Bb = ((size_t)uv*COUT + n0)*KW;

    auto stage = [&](int kc, int s){
        const uint32_t sb = sb0 + s*55296;
        const __nv_bfloat16* a_h = (kc < 4) ? A1h : A2h;
        const __nv_bfloat16* a_l = (kc < 4) ? A1l : A2l;
        const int kk = (kc & 3)*64;
#pragma unroll
        for (int u = 0; u < 12; u++){
            int idx = tid + (u << 8);
            const __nv_bfloat16* src; uint32_t dst;
            if (idx < 1024){
                int hl = idx >> 9, w = idx & 511, r = w >> 3, c = w & 7;
                src = (hl ? a_l : a_h) + Ao + (size_t)r*256 + kk + c*8;
                dst = sb + hl*9216 + (r*72 + c*8)*2;
            } else {
                int w = idx - 1024; int hl = w >> 10; w &= 1023;
                int r = w >> 3, c = w & 7;
                src = (hl ? Wl_g : Wh_g) + Bb + (size_t)r*KW + kc*64 + c*8;
                dst = sb + 18432 + hl*18432 + (r*72 + c*8)*2;
            }
            CP16(dst, src);
        }
        CPCOMMIT();
    };

    float acc[2][4][4];
#pragma unroll
    for (int mt = 0; mt < 2; mt++)
#pragma unroll
        for (int nf = 0; nf < 4; nf++)
#pragma unroll
            for (int e = 0; e < 4; e++) acc[mt][nf][e] = 0.f;

    const int lr = lane & 7, ls = lane >> 3;
    const int arow = ((ls & 1) << 3) + lr, acol = (ls >> 1) << 3;
    const int brow = ((ls >> 1) << 3) + lr, bcol = (ls & 1) << 3;
    const int wm = (wid & 1)*32, wn = (wid >> 1)*32;

    stage(0, 0);
#pragma unroll 1
    for (int kc = 0; kc < 8; kc++){
        if (kc < 7){ stage(kc+1, (kc+1) & 1); CPWAIT1(); } else CPWAIT0();
        __syncthreads();
        const uint32_t sA = sb0 + (kc & 1)*55296;
        const uint32_t sB = sA + 18432;
#pragma unroll
        for (int k16 = 0; k16 < 4; k16++){
            const int kcc = k16*16;
            uint32_t bh[4][2], bl[4][2];
#pragma unroll
            for (int g = 0; g < 2; g++){
                uint32_t tb[4];
                uint32_t ra = sB + ((wn + g*16 + brow)*72 + kcc + bcol)*2;
                LDSM4(tb, ra);
                bh[2*g][0]=tb[0]; bh[2*g][1]=tb[1]; bh[2*g+1][0]=tb[2]; bh[2*g+1][1]=tb[3];
                LDSM4(tb, ra + 18432);
                bl[2*g][0]=tb[0]; bl[2*g][1]=tb[1]; bl[2*g+1][0]=tb[2]; bl[2*g+1][1]=tb[3];
            }
#pragma unroll
            for (int mt = 0; mt < 2; mt++){
                uint32_t ah[4], al[4];
                uint32_t ra = sA + ((wm + mt*16 + arow)*72 + kcc + acol)*2;
                LDSM4(ah, ra);
                LDSM4(al, ra + 9216);
#pragma unroll
                for (int nf = 0; nf < 4; nf++){
                    MMA_BF16(acc[mt][nf], ah, bh[nf]);
                    MMA_BF16(acc[mt][nf], al, bh[nf]);
                    MMA_BF16(acc[mt][nf], ah, bl[nf]);
                }
            }
        }
        __syncthreads();
    }

    const int g2 = lane >> 2, cg = (lane & 3)*2;
#pragma unroll
    for (int nf = 0; nf < 4; nf++){
        int col = n0 + wn + nf*8 + cg;
#pragma unroll
        for (int mt = 0; mt < 2; mt++){
            int row = m0 + wm + mt*16 + g2;
            *(float2*)&Mout[((size_t)uv*MR + row)*COUT + col]     = make_float2(acc[mt][nf][0], acc[mt][nf][1]);
            *(float2*)&Mout[((size_t)uv*MR + row + 8)*COUT + col] = make_float2(acc[mt][nf][2], acc[mt][nf][3]);
        }
    }
}

// ---------------- F(4,3) output transform core -------------------------------
__device__ __forceinline__ void wino_out(const float m[6][6], float y[4][4]){
    float z[4][6];
#pragma unroll
    for (int c = 0; c < 6; c++){
        float m1 = m[1][c], m2 = m[2][c], m3 = m[3][c], m4 = m[4][c];
        z[0][c] = m[0][c] + m1 + m2 + m3 + m4;
        z[1][c] = m1 - m2 + 2.f*(m3 - m4);
        z[2][c] = m1 + m2 + 4.f*(m3 + m4);
        z[3][c] = m1 - m2 + 8.f*(m3 - m4) + m[5][c];
    }
#pragma unroll
    for (int r = 0; r < 4; r++){
        float v1 = z[r][1], v2 = z[r][2], v3 = z[r][3], v4 = z[r][4];
        y[r][0] = z[r][0] + v1 + v2 + v3 + v4;
        y[r][1] = v1 - v2 + 2.f*(v3 - v4);
        y[r][2] = v1 + v2 + 4.f*(v3 + v4);
        y[r][3] = v1 - v2 + 8.f*(v3 - v4) + z[r][5];
    }
}

// ---------------- attention output transform + fused e-partials -------------
__global__ void otrAe_k(const float* __restrict__ Msrc, const float* __restrict__ b1,
                        const float* __restrict__ b2, const float* __restrict__ Va){
    __shared__ float sEP[8][36];
    const int tt = blockIdx.x, co = threadIdx.x;
    const int rr = tt%80, ty = rr/10, tx = rr%10;
    float m[6][6];
#pragma unroll
    for (int uv = 0; uv < UV; uv++)
        m[uv/6][uv%6] = Msrc[((size_t)uv*MR + tt)*256 + co];
    float y[4][4];
    wino_out(m, y);
    const float bz = __ldg(b1 + co) + __ldg(b2 + co);

    float va[9];
#pragma unroll
    for (int k = 0; k < 9; k++) va[k] = __ldg(Va + k*C_ + co);

    float ep[6][6];
#pragma unroll
    for (int i = 0; i < 36; i++) ep[i/6][i%6] = 0.f;
#pragma unroll
    for (int r = 0; r < 4; r++){
        int oy = 4*ty + r;
        if (oy >= HH) continue;
#pragma unroll
        for (int c = 0; c < 4; c++){
            float av = tanhf(y[r][c] + bz);
#pragma unroll
            for (int d = -1; d <= 1; d++)
#pragma unroll
                for (int dd = -1; dd <= 1; dd++)
                    ep[r+1+d][c+1+dd] += av * va[(1-d)*3 + (1-dd)];
        }
    }
    const int lane = co & 31, wrp = co >> 5;
#pragma unroll
    for (int l = 0; l < 36; l++){
        float v = ep[l/6][l%6];
#pragma unroll
        for (int o = 16; o > 0; o >>= 1) v += __shfl_xor_sync(0xFFFFFFFF, v, o);
        if (lane == 0) sEP[wrp][l] = v;
    }
    __syncthreads();
    if (co < 36){
        float s = 0.f;
#pragma unroll
        for (int w = 0; w < 8; w++) s += sEP[w][co];
        g_ep[(size_t)tt*36 + co] = s;
    }
}

// ---------------- gate output transform + LSTM update (fused) ---------------
__global__ void otrl_k(const float* __restrict__ Msrc, const float* __restrict__ b1,
                       const float* __restrict__ b2, float* __restrict__ outp){
    const int tt = blockIdx.x, co = threadIdx.x;
    const int b = tt/80, rr = tt%80, ty = rr/10, tx = rr%10;
    float yg[4][4][4];
#pragma unroll
    for (int g = 0; g < 4; g++){
        float m[6][6];
#pragma unroll
        for (int uv = 0; uv < UV; uv++)
            m[uv/6][uv%6] = Msrc[((size_t)uv*MR + tt)*1024 + g*256 + co];
        wino_out(m, yg[g]);
    }
    float bz[4];
#pragma unroll
    for (int g = 0; g < 4; g++)
        bz[g] = __ldg(b1 + g*256 + co) + __ldg(b2 + g*256 + co);
#pragma unroll
    for (int r = 0; r < 4; r++){
        int oy = 4*ty + r;
        if (oy >= HH) continue;
#pragma unroll
        for (int c = 0; c < 4; c++){
            int px = 4*tx + c;
            int pix = (oy + 1)*PW2 + px + 1;
            size_t cx = ((size_t)(b*NP + pix))*C_ + co;
            float iv = 1.f/(1.f + expf(-(yg[0][r][c] + bz[0])));
            float fv = 1.f/(1.f + expf(-(yg[1][r][c] + bz[1])));
            float cc = tanhf(yg[2][r][c] + bz[2]);
            float ov = 1.f/(1.f + expf(-(yg[3][r][c] + bz[3])));
            float cn = fv*g_cS[cx] + iv*cc;
            float hn = ov*tanhf(cn);
            g_cS[cx] = cn;
            g_h32[cx] = hn;
            if (outp) outp[((size_t)(b*C_ + co))*HW_ + oy*WW + px] = hn;
        }
    }
}

// ---------------- h0 = c0 = sum_t x ------------------------------------------
__global__ void init_hc_k(){
    int i = blockIdx.x*blockDim.x + threadIdx.x;
    if (i >= BB*HW_*C_) return;
    int ci = i & 255, rest = i >> 8;
    int p = rest % HW_, b = rest / HW_;
    int q = (p/WW + 1)*PW2 + (p%WW) + 1;
    float s = 0.f;
#pragma unroll
    for (int t = 0; t < TT; t++)
        s += g_x32[(((size_t)t*BB + b)*NP + q)*C_ + ci];
    size_t o = ((size_t)b*NP + q)*C_ + ci;
    g_cS[o] = s;
    g_h32[o] = s;
}

// -----------------------------------------------------------------------------
extern "C" void kernel_launch(void* const* d_in, const int* in_sizes, int n_in,
                              void* d_out, int out_size)
{
    const float* x   = (const float*)d_in[0];
    const float* Wa  = (const float*)d_in[1];
    const float* ba  = (const float*)d_in[2];
    const float* Ua  = (const float*)d_in[3];
    const float* bua = (const float*)d_in[4];
    const float* Va  = (const float*)d_in[5];
    const float* Wx  = (const float*)d_in[6];
    const float* bx  = (const float*)d_in[7];
    const float* Uh  = (const float*)d_in[8];
    const float* bh  = (const float*)d_in[9];
    float* out = (float*)d_out;

    void *pX, *pWAh, *pWAl, *pWGh, *pWGl, *pM, *pMa;
    void *pUHh, *pUHl, *pUXh, *pUXl, *pUTh, *pUTl;
    cudaGetSymbolAddress(&pX,  g_x32);
    cudaGetSymbolAddress(&pWAh, g_WAh); cudaGetSymbolAddress(&pWAl, g_WAl);
    cudaGetSymbolAddress(&pWGh, g_WGh); cudaGetSymbolAddress(&pWGl, g_WGl);
    cudaGetSymbolAddress(&pM,  g_M);    cudaGetSymbolAddress(&pMa, g_Ma);
    cudaGetSymbolAddress(&pUHh, g_UHh); cudaGetSymbolAddress(&pUHl, g_UHl);
    cudaGetSymbolAddress(&pUXh, g_UXh); cudaGetSymbolAddress(&pUXl, g_UXl);
    cudaGetSymbolAddress(&pUTh, g_UTh); cudaGetSymbolAddress(&pUTl, g_UTl);

    const int SMEM = 2*55296;   // 110,592 B double-buffered stage
    cudaFuncSetAttribute(gemm_k<256>,  cudaFuncAttributeMaxDynamicSharedMemorySize, SMEM);
    cudaFuncSetAttribute(gemm_k<1024>, cudaFuncAttributeMaxDynamicSharedMemorySize, SMEM);

    // NOTE: no memsets needed — device globals are zero-initialized at module
    // load; pad borders of g_x32/g_h32 are never written, interiors are fully
    // rewritten each call (deterministic).

    xprep_k<<<dim3(38, 8, 16), dim3(32, 8)>>>(x);
    wtr_k<<<dim3(8,  8), dim3(32, 8)>>>(Wa, 256,  0, (__nv_bfloat16*)pWAh, (__nv_bfloat16*)pWAl);
    wtr_k<<<dim3(8,  8), dim3(32, 8)>>>(Ua, 256,  1, (__nv_bfloat16*)pWAh, (__nv_bfloat16*)pWAl);
    wtr_k<<<dim3(32, 8), dim3(32, 8)>>>(Uh, 1024, 0, (__nv_bfloat16*)pWGh, (__nv_bfloat16*)pWGl);
    wtr_k<<<dim3(32, 8), dim3(32, 8)>>>(Wx, 1024, 1, (__nv_bfloat16*)pWGh, (__nv_bfloat16*)pWGl);

    const int NPT = BB*HW_*C_, NB = (NPT + 255)/256;
    init_hc_k<<<NB, 256>>>();
    itrXall_k<<<dim3(TLS, TT), 256>>>();   // all x_t transforms, once

    const float* x32 = (const float*)pX;
    const size_t ts = (size_t)BB*NP*C_;

    for (int t = 0; t < TT; t++){
        // attention: att = tanh(conv(h,Wa)+ba + conv(x_t,Ua)+bua); e fused into otrAe
        itrH_k<<<TLS, 256>>>();
        gemm_k<256><<<dim3(5, 2, UV), 256, SMEM>>>(
            (const __nv_bfloat16*)pUHh, (const __nv_bfloat16*)pUHl,
            (const __nv_bfloat16*)pUXh + t*USLAB, (const __nv_bfloat16*)pUXl + t*USLAB,
            (const __nv_bfloat16*)pWAh, (const __nv_bfloat16*)pWAl, (float*)pMa);
        otrAe_k<<<TLS, 256>>>((const float*)pMa, ba, bua, Va);

        // fused softmax + x_tilde transform
        itrXs_k<<<TLS, 256>>>(x32 + t*ts);

        // gates: g = conv(x*a,Wx)+bx + conv(h,Uh)+bh ; then LSTM update
        gemm_k<1024><<<dim3(5, 8, UV), 256, SMEM>>>(
            (const __nv_bfloat16*)pUHh, (const __nv_bfloat16*)pUHl,
            (const __nv_bfloat16*)pUTh, (const __nv_bfloat16*)pUTl,
            (const __nv_bfloat16*)pWGh, (const __nv_bfloat16*)pWGl, (float*)pM);
        otrl_k<<<TLS, 256>>>((const float*)pM, bx, bh, (t == TT-1) ? out : (float*)nullptr);
    }
}